// round 1
// baseline (speedup 1.0000x reference)
#include <cuda_runtime.h>
#include <math.h>

// Problem constants
#define NN 8192
#define FF 256
#define NH 4
#define DD 128
#define CC 512          // NH*DD feature columns
#define CP 544          // padded: 512 num cols + 4 den cols + 28 zero pad

// Scratch (device globals: no allocation allowed)
__device__ float g_ht[(size_t)NN * CC];   // 16 MB   lrelu(h@W), row-major [j][c]
__device__ float g_tgt[NH * NN];
__device__ float g_mh[NH];
__device__ float g_V[(size_t)NN * CP];    // 17.8 MB weighted features + w cols
__device__ float g_O[(size_t)NN * CP];    // 17.8 MB A @ V

// ---------------------------------------------------------------------------
// Kernel 1: ht = leakyrelu(h @ W)   [8192x256]@[256x512]
// Block tile 64x128, Kc=32, 256 threads, thread tile 8x4
// ---------------------------------------------------------------------------
__global__ __launch_bounds__(256) void k_proj(const float* __restrict__ h,
                                              const float* __restrict__ W) {
    __shared__ float As[32][64];    // [kk][m]
    __shared__ float Bs[32][128];   // [kk][n]
    const int tid = threadIdx.x;
    const int m0 = blockIdx.x * 64;
    const int n0 = blockIdx.y * 128;
    const int trow = tid >> 5;      // 0..7
    const int tcol = tid & 31;      // 0..31

    float acc[8][4];
#pragma unroll
    for (int r = 0; r < 8; r++)
#pragma unroll
        for (int n = 0; n < 4; n++) acc[r][n] = 0.f;

    for (int k0 = 0; k0 < FF; k0 += 32) {
        // load A tile (h): 64 rows x 32 k
        {
            const int r = tid >> 2;
            const int kc = (tid & 3) * 8;
            const float4* src = reinterpret_cast<const float4*>(
                h + (size_t)(m0 + r) * FF + k0 + kc);
            float4 v0 = src[0], v1 = src[1];
            As[kc + 0][r] = v0.x; As[kc + 1][r] = v0.y;
            As[kc + 2][r] = v0.z; As[kc + 3][r] = v0.w;
            As[kc + 4][r] = v1.x; As[kc + 5][r] = v1.y;
            As[kc + 6][r] = v1.z; As[kc + 7][r] = v1.w;
        }
        // load B tile (W): 32 x 128
#pragma unroll
        for (int idx = tid * 4; idx < 32 * 128; idx += 1024) {
            const int kk = idx >> 7;
            const int n = idx & 127;
            *reinterpret_cast<float4*>(&Bs[kk][n]) =
                *reinterpret_cast<const float4*>(W + (size_t)(k0 + kk) * CC + n0 + n);
        }
        __syncthreads();

#pragma unroll
        for (int kk = 0; kk < 32; kk++) {
            float4 a0 = *reinterpret_cast<float4*>(&As[kk][trow * 8]);
            float4 a1 = *reinterpret_cast<float4*>(&As[kk][trow * 8 + 4]);
            float4 bb = *reinterpret_cast<float4*>(&Bs[kk][tcol * 4]);
            float am[8] = {a0.x, a0.y, a0.z, a0.w, a1.x, a1.y, a1.z, a1.w};
            float bn[4] = {bb.x, bb.y, bb.z, bb.w};
#pragma unroll
            for (int r = 0; r < 8; r++)
#pragma unroll
                for (int n = 0; n < 4; n++) acc[r][n] += am[r] * bn[n];
        }
        __syncthreads();
    }
    // epilogue: leaky relu, store
#pragma unroll
    for (int r = 0; r < 8; r++) {
        const size_t off = (size_t)(m0 + trow * 8 + r) * CC + n0 + tcol * 4;
        float4 o;
        float x;
        x = acc[r][0]; o.x = (x >= 0.f) ? x : 0.1f * x;
        x = acc[r][1]; o.y = (x >= 0.f) ? x : 0.1f * x;
        x = acc[r][2]; o.z = (x >= 0.f) ? x : 0.1f * x;
        x = acc[r][3]; o.w = (x >= 0.f) ? x : 0.1f * x;
        *reinterpret_cast<float4*>(&g_ht[off]) = o;
    }
}

// ---------------------------------------------------------------------------
// Kernel 2: tgt[h][j] = ht[j, h*128:d] . a[h, 128+d]   (warp per (j,h))
// ---------------------------------------------------------------------------
__global__ __launch_bounds__(256) void k_tgt(const float* __restrict__ a) {
    const int gw = blockIdx.x * 8 + (threadIdx.x >> 5);
    const int lane = threadIdx.x & 31;
    const int h = gw & 3;
    const int j = gw >> 2;
    float4 x = *reinterpret_cast<const float4*>(g_ht + (size_t)j * CC + h * DD + lane * 4);
    float4 av = *reinterpret_cast<const float4*>(a + h * 256 + 128 + lane * 4);
    float s = x.x * av.x + x.y * av.y + x.z * av.z + x.w * av.w;
#pragma unroll
    for (int o = 16; o; o >>= 1) s += __shfl_xor_sync(0xFFFFFFFFu, s, o);
    if (lane == 0) g_tgt[h * NN + j] = s;
}

// ---------------------------------------------------------------------------
// Kernel 3: per-head max of tgt (one block per head, no atomics/init needed)
// ---------------------------------------------------------------------------
__global__ __launch_bounds__(256) void k_max() {
    __shared__ float red[256];
    const int h = blockIdx.x;
    const int tid = threadIdx.x;
    float m = -1e30f;
    for (int j = tid; j < NN; j += 256) m = fmaxf(m, g_tgt[h * NN + j]);
    red[tid] = m;
    __syncthreads();
#pragma unroll
    for (int s = 128; s; s >>= 1) {
        if (tid < s) red[tid] = fmaxf(red[tid], red[tid + s]);
        __syncthreads();
    }
    if (tid == 0) g_mh[h] = red[0];
}

// ---------------------------------------------------------------------------
// Kernel 4: build V[j][c]: cols 0..511 = w_h*ht, 512..515 = w_h, 516..543 = 0
// ---------------------------------------------------------------------------
__global__ __launch_bounds__(256) void k_buildV() {
    const int j = blockIdx.x;
    const int tid = threadIdx.x;
    __shared__ float w[4];
    if (tid < 4) w[tid] = expf(g_tgt[tid * NN + j] - g_mh[tid]);
    __syncthreads();
    for (int c = tid; c < CP; c += 256) {
        float v;
        if (c < CC)            v = w[c >> 7] * g_ht[(size_t)j * CC + c];
        else if (c < CC + NH)  v = w[c - CC];
        else                   v = 0.f;
        g_V[(size_t)j * CP + c] = v;
    }
}

// ---------------------------------------------------------------------------
// Kernel 5: O = float(adj) @ V      (the big one: 8192x8192x{512|32})
// Block tile 64 x NTILE, Kc=32, 256 threads, thread tile 8 x TN
// ---------------------------------------------------------------------------
template <int NTILE, int TN>
__global__ __launch_bounds__(256) void k_aggr(const int* __restrict__ A, int n0base) {
    __shared__ float As[32][64];       // [kk][m]
    __shared__ float Bs[32][NTILE];    // [kk][n]
    const int tid = threadIdx.x;
    const int m0 = blockIdx.x * 64;
    const int n0 = n0base + blockIdx.y * NTILE;
    const int trow = tid >> 5;
    const int tcol = tid & 31;

    float acc[8][TN];
#pragma unroll
    for (int r = 0; r < 8; r++)
#pragma unroll
        for (int n = 0; n < TN; n++) acc[r][n] = 0.f;

    for (int k0 = 0; k0 < NN; k0 += 32) {
        // load adjacency tile 64x32 (int -> float)
        {
            const int r = tid >> 2;
            const int kc = (tid & 3) * 8;
            const int4* src = reinterpret_cast<const int4*>(
                A + (size_t)(m0 + r) * NN + k0 + kc);
            int4 v0 = src[0], v1 = src[1];
            As[kc + 0][r] = (float)v0.x; As[kc + 1][r] = (float)v0.y;
            As[kc + 2][r] = (float)v0.z; As[kc + 3][r] = (float)v0.w;
            As[kc + 4][r] = (float)v1.x; As[kc + 5][r] = (float)v1.y;
            As[kc + 6][r] = (float)v1.z; As[kc + 7][r] = (float)v1.w;
        }
        // load V tile 32 x NTILE
#pragma unroll
        for (int idx = tid * 4; idx < 32 * NTILE; idx += 1024) {
            const int kk = idx / NTILE;
            const int n = idx % NTILE;
            *reinterpret_cast<float4*>(&Bs[kk][n]) =
                *reinterpret_cast<const float4*>(g_V + (size_t)(k0 + kk) * CP + n0 + n);
        }
        __syncthreads();

#pragma unroll
        for (int kk = 0; kk < 32; kk++) {
            float4 a0 = *reinterpret_cast<float4*>(&As[kk][trow * 8]);
            float4 a1 = *reinterpret_cast<float4*>(&As[kk][trow * 8 + 4]);
            float am[8] = {a0.x, a0.y, a0.z, a0.w, a1.x, a1.y, a1.z, a1.w};
            float bn[TN];
            if (TN == 4) {
                float4 bb = *reinterpret_cast<float4*>(&Bs[kk][tcol * 4]);
                bn[0] = bb.x; bn[1] = bb.y; bn[2] = bb.z; bn[3] = bb.w;
            } else {
                bn[0] = Bs[kk][tcol];
            }
#pragma unroll
            for (int r = 0; r < 8; r++)
#pragma unroll
                for (int n = 0; n < TN; n++) acc[r][n] += am[r] * bn[n];
        }
        __syncthreads();
    }

#pragma unroll
    for (int r = 0; r < 8; r++) {
        const size_t off = (size_t)(m0 + trow * 8 + r) * CP + n0 + tcol * TN;
#pragma unroll
        for (int n = 0; n < TN; n++) g_O[off + n] = acc[r][n];
    }
}

// ---------------------------------------------------------------------------
// Kernel 6: out[i][d] = 0.25 * sum_h num[h]/den[h]
// ---------------------------------------------------------------------------
__global__ __launch_bounds__(128) void k_out(float* __restrict__ out) {
    const int i = blockIdx.x;
    const int d = threadIdx.x;
    __shared__ float inv[4];
    if (d < 4) inv[d] = 1.0f / g_O[(size_t)i * CP + CC + d];
    __syncthreads();
    float s = 0.f;
#pragma unroll
    for (int h = 0; h < 4; h++) s += g_O[(size_t)i * CP + h * DD + d] * inv[h];
    out[(size_t)i * DD + d] = 0.25f * s;
}

// ---------------------------------------------------------------------------
extern "C" void kernel_launch(void* const* d_in, const int* in_sizes, int n_in,
                              void* d_out, int out_size) {
    const float* h   = (const float*)d_in[0];
    const int*   adj = (const int*)d_in[1];
    const float* W   = (const float*)d_in[2];
    const float* a   = (const float*)d_in[3];
    float* out = (float*)d_out;

    k_proj<<<dim3(128, 4), 256>>>(h, W);        // g_ht
    k_tgt<<<4096, 256>>>(a);                    // g_tgt
    k_max<<<4, 256>>>();                        // g_mh
    k_buildV<<<8192, 256>>>();                  // g_V
    k_aggr<128, 4><<<dim3(128, 4), 256>>>(adj, 0);    // num cols 0..511
    k_aggr<32, 1><<<dim3(128, 1), 256>>>(adj, 512);   // den cols 512..543
    k_out<<<8192, 128>>>(out);
}

// round 3
// speedup vs baseline: 4.3414x; 4.3414x over previous
#include <cuda_runtime.h>
#include <cuda_fp16.h>
#include <math.h>
#include <stdint.h>

// Problem constants
#define NN 8192
#define FF 256
#define DD 128
#define CC 512          // NH*DD feature columns
#define NP 640          // padded GEMM N: 512 num + 4 den + 124 zero (5 x 128 tiles)

// aggr GEMM tiling
#define KST 64                  // fp16 K elements per stage
#define NST 3                   // pipeline stages
#define ROWB 144                // padded smem row bytes (64*2 + 16)
#define OPBYTES (128 * ROWB)    // 18432 per operand per stage
#define STAGE (2 * OPBYTES)     // 36864
#define SMEMB (NST * STAGE)     // 110592

// Scratch (device globals: no allocation allowed)
__device__ float  g_ht[(size_t)NN * CC];    // 16 MB  lrelu(h@W)
__device__ float  g_tgt[4 * NN];
__device__ float  g_w[4 * NN];
__device__ float  g_mh[4];
__device__ __half g_Ah[(size_t)NN * NN];    // 128 MB adjacency as fp16
__device__ __half g_VT[(size_t)NP * NN];    // 10 MB  V transposed, K-major [n][k]
__device__ float  g_O[(size_t)NN * NP];     // 20 MB  A @ V

// ---------------------------------------------------------------------------
// helpers (sm_80-compatible PTX only: mma.sync / ldmatrix / cp.async)
// ---------------------------------------------------------------------------
__device__ __forceinline__ uint32_t smem_u32(const void* p) {
    uint32_t a;
    asm("{ .reg .u64 t; cvta.to.shared.u64 t, %1; cvt.u32.u64 %0, t; }" : "=r"(a) : "l"(p));
    return a;
}
static __device__ __forceinline__ void cp16(uint32_t dst, const void* src) {
    asm volatile("cp.async.cg.shared.global [%0], [%1], 16;" :: "r"(dst), "l"(src));
}
static __device__ __forceinline__ void cp_commit() {
    asm volatile("cp.async.commit_group;" ::: "memory");
}
__device__ __forceinline__ void ldsm4(uint32_t& r0, uint32_t& r1, uint32_t& r2,
                                      uint32_t& r3, uint32_t addr) {
    asm volatile("ldmatrix.sync.aligned.m8n8.x4.shared.b16 {%0,%1,%2,%3}, [%4];"
                 : "=r"(r0), "=r"(r1), "=r"(r2), "=r"(r3) : "r"(addr));
}
__device__ __forceinline__ void mma16816(float* d, const uint32_t* a,
                                         uint32_t b0, uint32_t b1) {
    asm volatile("mma.sync.aligned.m16n8k16.row.col.f32.f16.f16.f32 "
                 "{%0,%1,%2,%3}, {%4,%5,%6,%7}, {%8,%9}, {%0,%1,%2,%3};"
                 : "+f"(d[0]), "+f"(d[1]), "+f"(d[2]), "+f"(d[3])
                 : "r"(a[0]), "r"(a[1]), "r"(a[2]), "r"(a[3]), "r"(b0), "r"(b1));
}

// ---------------------------------------------------------------------------
// Kernel 0: convert adjacency int32 -> fp16
// ---------------------------------------------------------------------------
__global__ __launch_bounds__(256) void k_conv(const int* __restrict__ A) {
    size_t idx = ((size_t)blockIdx.x * 256 + threadIdx.x) * 8;
    int4 a = *reinterpret_cast<const int4*>(A + idx);
    int4 b = *reinterpret_cast<const int4*>(A + idx + 4);
    __half2 h[4];
    h[0] = __halves2half2(__int2half_rn(a.x), __int2half_rn(a.y));
    h[1] = __halves2half2(__int2half_rn(a.z), __int2half_rn(a.w));
    h[2] = __halves2half2(__int2half_rn(b.x), __int2half_rn(b.y));
    h[3] = __halves2half2(__int2half_rn(b.z), __int2half_rn(b.w));
    *reinterpret_cast<uint4*>(g_Ah + idx) = *reinterpret_cast<uint4*>(h);
}

// ---------------------------------------------------------------------------
// Kernel 1: ht = leakyrelu(h @ W)   [8192x256]@[256x512]
// ---------------------------------------------------------------------------
__global__ __launch_bounds__(256) void k_proj(const float* __restrict__ h,
                                              const float* __restrict__ W) {
    __shared__ float As[32][64];
    __shared__ float Bs[32][128];
    const int tid = threadIdx.x;
    const int m0 = blockIdx.x * 64;
    const int n0 = blockIdx.y * 128;
    const int trow = tid >> 5;
    const int tcol = tid & 31;

    float acc[8][4];
#pragma unroll
    for (int r = 0; r < 8; r++)
#pragma unroll
        for (int n = 0; n < 4; n++) acc[r][n] = 0.f;

    for (int k0 = 0; k0 < FF; k0 += 32) {
        {
            const int r = tid >> 2;
            const int kc = (tid & 3) * 8;
            const float4* src = reinterpret_cast<const float4*>(
                h + (size_t)(m0 + r) * FF + k0 + kc);
            float4 v0 = src[0], v1 = src[1];
            As[kc + 0][r] = v0.x; As[kc + 1][r] = v0.y;
            As[kc + 2][r] = v0.z; As[kc + 3][r] = v0.w;
            As[kc + 4][r] = v1.x; As[kc + 5][r] = v1.y;
            As[kc + 6][r] = v1.z; As[kc + 7][r] = v1.w;
        }
#pragma unroll
        for (int idx = tid * 4; idx < 32 * 128; idx += 1024) {
            const int kk = idx >> 7;
            const int n = idx & 127;
            *reinterpret_cast<float4*>(&Bs[kk][n]) =
                *reinterpret_cast<const float4*>(W + (size_t)(k0 + kk) * CC + n0 + n);
        }
        __syncthreads();
#pragma unroll
        for (int kk = 0; kk < 32; kk++) {
            float4 a0 = *reinterpret_cast<float4*>(&As[kk][trow * 8]);
            float4 a1 = *reinterpret_cast<float4*>(&As[kk][trow * 8 + 4]);
            float4 bb = *reinterpret_cast<float4*>(&Bs[kk][tcol * 4]);
            float am[8] = {a0.x, a0.y, a0.z, a0.w, a1.x, a1.y, a1.z, a1.w};
            float bn[4] = {bb.x, bb.y, bb.z, bb.w};
#pragma unroll
            for (int r = 0; r < 8; r++)
#pragma unroll
                for (int n = 0; n < 4; n++) acc[r][n] += am[r] * bn[n];
        }
        __syncthreads();
    }
#pragma unroll
    for (int r = 0; r < 8; r++) {
        const size_t off = (size_t)(m0 + trow * 8 + r) * CC + n0 + tcol * 4;
        float4 o; float x;
        x = acc[r][0]; o.x = (x >= 0.f) ? x : 0.1f * x;
        x = acc[r][1]; o.y = (x >= 0.f) ? x : 0.1f * x;
        x = acc[r][2]; o.z = (x >= 0.f) ? x : 0.1f * x;
        x = acc[r][3]; o.w = (x >= 0.f) ? x : 0.1f * x;
        *reinterpret_cast<float4*>(&g_ht[off]) = o;
    }
}

// ---------------------------------------------------------------------------
// Kernel 2: tgt[h][j] = ht[j, h*128:] . a[h, 128+..]
// ---------------------------------------------------------------------------
__global__ __launch_bounds__(256) void k_tgt(const float* __restrict__ a) {
    const int gw = blockIdx.x * 8 + (threadIdx.x >> 5);
    const int lane = threadIdx.x & 31;
    const int h = gw & 3;
    const int j = gw >> 2;
    float4 x = *reinterpret_cast<const float4*>(g_ht + (size_t)j * CC + h * DD + lane * 4);
    float4 av = *reinterpret_cast<const float4*>(a + h * 256 + 128 + lane * 4);
    float s = x.x * av.x + x.y * av.y + x.z * av.z + x.w * av.w;
#pragma unroll
    for (int o = 16; o; o >>= 1) s += __shfl_xor_sync(0xFFFFFFFFu, s, o);
    if (lane == 0) g_tgt[h * NN + j] = s;
}

// ---------------------------------------------------------------------------
// Kernel 3: per-head max of tgt
// ---------------------------------------------------------------------------
__global__ __launch_bounds__(256) void k_max() {
    __shared__ float red[256];
    const int h = blockIdx.x;
    const int tid = threadIdx.x;
    float m = -1e30f;
    for (int j = tid; j < NN; j += 256) m = fmaxf(m, g_tgt[h * NN + j]);
    red[tid] = m;
    __syncthreads();
#pragma unroll
    for (int s = 128; s; s >>= 1) {
        if (tid < s) red[tid] = fmaxf(red[tid], red[tid + s]);
        __syncthreads();
    }
    if (tid == 0) g_mh[h] = red[0];
}

// ---------------------------------------------------------------------------
// Kernel 4: w[h][j] = exp(tgt - mh)
// ---------------------------------------------------------------------------
__global__ __launch_bounds__(256) void k_expw() {
    int idx = blockIdx.x * 256 + threadIdx.x;
    int h = idx >> 13;
    g_w[idx] = expf(g_tgt[idx] - g_mh[h]);
}

// ---------------------------------------------------------------------------
// Kernel 5: build transposed fp16 V:  g_VT[n][j]
// ---------------------------------------------------------------------------
__global__ __launch_bounds__(256) void k_buildVT() {
    __shared__ float ts[32][129];
    const int tid = threadIdx.x;
    const int j0 = blockIdx.x * 128;
    const int n0 = blockIdx.y * 32;

    if (n0 >= CC) {
#pragma unroll
        for (int r = 0; r < 2; r++) {
            int v = r * 256 + tid;
            int nl = v >> 4;
            int j8 = (v & 15) * 8;
            int n = n0 + nl;
            __half out[8];
            if (n < CC + 4) {
                const float* ws = g_w + (size_t)(n - CC) * NN + j0 + j8;
#pragma unroll
                for (int e = 0; e < 8; e++) out[e] = __float2half(ws[e]);
            } else {
#pragma unroll
                for (int e = 0; e < 8; e++) out[e] = __float2half(0.f);
            }
            *reinterpret_cast<uint4*>(g_VT + (size_t)n * NN + j0 + j8) =
                *reinterpret_cast<uint4*>(out);
        }
        return;
    }
#pragma unroll
    for (int r = 0; r < 16; r++) {
        int idx = r * 256 + tid;
        int jl = idx >> 5;
        int nl = idx & 31;
        ts[nl][jl] = g_ht[(size_t)(j0 + jl) * CC + n0 + nl];
    }
    __syncthreads();
    const int h = n0 >> 7;
#pragma unroll
    for (int r = 0; r < 2; r++) {
        int v = r * 256 + tid;
        int nl = v >> 4;
        int j8 = (v & 15) * 8;
        __half out[8];
#pragma unroll
        for (int e = 0; e < 8; e++)
            out[e] = __float2half(ts[nl][j8 + e] * g_w[(size_t)h * NN + j0 + j8 + e]);
        *reinterpret_cast<uint4*>(g_VT + (size_t)(n0 + nl) * NN + j0 + j8) =
            *reinterpret_cast<uint4*>(out);
    }
}

// ---------------------------------------------------------------------------
// Kernel 6: O = A @ V via mma.sync (M=8192, N=640, K=8192, fp16->f32)
// CTA 128x128, 8 warps (4x2), warp tile 32x64, K-stage 64, 3-stage cp.async
// ---------------------------------------------------------------------------
__device__ __forceinline__ void load_stage64(int t, uint32_t sb, int m0, int n0, int tid) {
    const int k0 = t * KST;
    const uint32_t base = sb + (t % NST) * STAGE;
#pragma unroll
    for (int i = 0; i < 8; i++) {
        int idx = i * 256 + tid;
        int op = idx >> 10;            // 0=A, 1=B
        int r  = (idx >> 3) & 127;     // row
        int c  = idx & 7;              // 16B chunk (8 halves)
        const __half* src = (op ? g_VT + (size_t)(n0 + r) * NN
                                : g_Ah + (size_t)(m0 + r) * NN) + k0 + c * 8;
        cp16(base + op * OPBYTES + r * ROWB + c * 16, src);
    }
}

__global__ __launch_bounds__(256, 2) void k_aggr_mma() {
    extern __shared__ __align__(128) char smem[];
    const uint32_t sb = smem_u32(smem);
    const int tid = threadIdx.x;
    const int lane = tid & 31;
    const int wid = tid >> 5;
    const int wm = wid & 3;        // warp m index (0..3) -> 32 rows
    const int wn = wid >> 2;       // warp n index (0..1) -> 64 cols
    const int m0 = blockIdx.x * 128;
    const int n0 = blockIdx.y * 128;

    float acc[2][8][4];
#pragma unroll
    for (int f = 0; f < 2; f++)
#pragma unroll
        for (int g = 0; g < 8; g++)
#pragma unroll
            for (int e = 0; e < 4; e++) acc[f][g][e] = 0.f;

#pragma unroll
    for (int s = 0; s < NST; s++) {
        load_stage64(s, sb, m0, n0, tid);
        cp_commit();
    }

    const int lr = lane & 15;          // ldmatrix row-within-frag
    const int lk = (lane >> 4) * 8;    // ldmatrix k-half offset

    const int S = NN / KST;  // 128
    for (int s = 0; s < S; s++) {
        asm volatile("cp.async.wait_group %0;" :: "n"(NST - 1) : "memory");
        __syncthreads();
        const uint32_t st = sb + (s % NST) * STAGE;
#pragma unroll
        for (int kk = 0; kk < KST / 16; kk++) {
            uint32_t af[2][4], bf[4][4];
#pragma unroll
            for (int f = 0; f < 2; f++) {
                int r = wm * 32 + f * 16 + lr;
                int k = kk * 16 + lk;
                ldsm4(af[f][0], af[f][1], af[f][2], af[f][3], st + r * ROWB + k * 2);
            }
#pragma unroll
            for (int g = 0; g < 4; g++) {
                int n = wn * 64 + g * 16 + lr;
                int k = kk * 16 + lk;
                ldsm4(bf[g][0], bf[g][1], bf[g][2], bf[g][3],
                      st + OPBYTES + n * ROWB + k * 2);
            }
#pragma unroll
            for (int f = 0; f < 2; f++)
#pragma unroll
                for (int g = 0; g < 4; g++) {
                    mma16816(acc[f][g * 2 + 0], af[f], bf[g][0], bf[g][2]);
                    mma16816(acc[f][g * 2 + 1], af[f], bf[g][1], bf[g][3]);
                }
        }
        __syncthreads();
        if (s + NST < S) {
            load_stage64(s + NST, sb, m0, n0, tid);
            cp_commit();
        }
    }

    // epilogue: write f32 accumulators
#pragma unroll
    for (int f = 0; f < 2; f++) {
        const int row = m0 + wm * 32 + f * 16 + (lane >> 2);
#pragma unroll
        for (int g = 0; g < 8; g++) {
            const int col = n0 + wn * 64 + g * 8 + (lane & 3) * 2;
            float2 v0 = {acc[f][g][0], acc[f][g][1]};
            float2 v1 = {acc[f][g][2], acc[f][g][3]};
            *reinterpret_cast<float2*>(g_O + (size_t)row * NP + col) = v0;
            *reinterpret_cast<float2*>(g_O + (size_t)(row + 8) * NP + col) = v1;
        }
    }
}

// ---------------------------------------------------------------------------
// Kernel 7: out[i][d] = 0.25 * sum_h num[h]/den[h]
// ---------------------------------------------------------------------------
__global__ __launch_bounds__(128) void k_out(float* __restrict__ out) {
    const int i = blockIdx.x;
    const int d = threadIdx.x;
    __shared__ float inv[4];
    if (d < 4) inv[d] = 1.0f / g_O[(size_t)i * NP + CC + d];
    __syncthreads();
    float s = 0.f;
#pragma unroll
    for (int h = 0; h < 4; h++) s += g_O[(size_t)i * NP + h * DD + d] * inv[h];
    out[(size_t)i * DD + d] = 0.25f * s;
}

// ---------------------------------------------------------------------------
extern "C" void kernel_launch(void* const* d_in, const int* in_sizes, int n_in,
                              void* d_out, int out_size) {
    const float* h   = (const float*)d_in[0];
    const int*   adj = (const int*)d_in[1];
    const float* W   = (const float*)d_in[2];
    const float* a   = (const float*)d_in[3];
    float* out = (float*)d_out;

    static int attr_done = 0;
    if (!attr_done) {
        cudaFuncSetAttribute(k_aggr_mma, cudaFuncAttributeMaxDynamicSharedMemorySize, SMEMB);
        attr_done = 1;
    }

    k_conv<<<32768, 256>>>(adj);
    k_proj<<<dim3(128, 4), 256>>>(h, W);
    k_tgt<<<4096, 256>>>(a);
    k_max<<<4, 256>>>();
    k_expw<<<128, 256>>>();
    k_buildVT<<<dim3(64, 20), 256>>>();
    k_aggr_mma<<<dim3(64, 5), 256, SMEMB>>>();
    k_out<<<8192, 128>>>(out);
}

// round 4
// speedup vs baseline: 5.6850x; 1.3095x over previous
#include <cuda_runtime.h>
#include <cuda_fp16.h>
#include <math.h>
#include <stdint.h>

// Problem constants
#define NN 8192
#define FF 256
#define DD 128
#define CC 512          // NH*DD feature columns (GEMM N = 512 exactly)

// aggr GEMM tiling: CTA 256x128, 8 warps (4m x 2n), warp tile 64x64
#define KST 64                    // fp16 K elements per stage
#define NST 3                     // pipeline stages
#define ROWB 144                  // padded smem row bytes (64*2 + 16)
#define A_ROWS 256
#define B_ROWS 128
#define B2_ROWS 16
#define A_BYTES (A_ROWS * ROWB)   // 36864
#define B_BYTES (B_ROWS * ROWB)   // 18432
#define B2_BYTES (B2_ROWS * ROWB) // 2304
#define STAGE (A_BYTES + B_BYTES + B2_BYTES)  // 57600
#define SMEMB (NST * STAGE)       // 172800

// Scratch (device globals: no allocation allowed)
__device__ float  g_ht[(size_t)NN * CC];    // 16 MB  lrelu(h@W)
__device__ float  g_tgt[4 * NN];
__device__ float  g_w[4 * NN];
__device__ float  g_mh[4];
__device__ __half g_wT[16 * NN];            // fp16 w, rows 4..15 zero
__device__ __half g_Ah[(size_t)NN * NN];    // 128 MB adjacency as fp16
__device__ __half g_VT[(size_t)CC * NN];    // 8 MB   V transposed, K-major [n][k]
__device__ float  g_O[(size_t)NN * CC];     // 16 MB  A @ V (numerators)
__device__ float  g_den[NN * 4];            // denominators

// ---------------------------------------------------------------------------
// helpers (sm_80-compatible PTX only)
// ---------------------------------------------------------------------------
__device__ __forceinline__ uint32_t smem_u32(const void* p) {
    uint32_t a;
    asm("{ .reg .u64 t; cvta.to.shared.u64 t, %1; cvt.u32.u64 %0, t; }" : "=r"(a) : "l"(p));
    return a;
}
static __device__ __forceinline__ void cp16(uint32_t dst, const void* src) {
    asm volatile("cp.async.cg.shared.global [%0], [%1], 16;" :: "r"(dst), "l"(src));
}
static __device__ __forceinline__ void cp_commit() {
    asm volatile("cp.async.commit_group;" ::: "memory");
}
__device__ __forceinline__ void ldsm4(uint32_t& r0, uint32_t& r1, uint32_t& r2,
                                      uint32_t& r3, uint32_t addr) {
    asm volatile("ldmatrix.sync.aligned.m8n8.x4.shared.b16 {%0,%1,%2,%3}, [%4];"
                 : "=r"(r0), "=r"(r1), "=r"(r2), "=r"(r3) : "r"(addr));
}
__device__ __forceinline__ void mma16816(float* d, const uint32_t* a,
                                         uint32_t b0, uint32_t b1) {
    asm volatile("mma.sync.aligned.m16n8k16.row.col.f32.f16.f16.f32 "
                 "{%0,%1,%2,%3}, {%4,%5,%6,%7}, {%8,%9}, {%0,%1,%2,%3};"
                 : "+f"(d[0]), "+f"(d[1]), "+f"(d[2]), "+f"(d[3])
                 : "r"(a[0]), "r"(a[1]), "r"(a[2]), "r"(a[3]), "r"(b0), "r"(b1));
}

// ---------------------------------------------------------------------------
// Kernel 0: convert adjacency int32 -> fp16
// ---------------------------------------------------------------------------
__global__ __launch_bounds__(256) void k_conv(const int* __restrict__ A) {
    size_t idx = ((size_t)blockIdx.x * 256 + threadIdx.x) * 8;
    int4 a = *reinterpret_cast<const int4*>(A + idx);
    int4 b = *reinterpret_cast<const int4*>(A + idx + 4);
    __half2 h[4];
    h[0] = __halves2half2(__int2half_rn(a.x), __int2half_rn(a.y));
    h[1] = __halves2half2(__int2half_rn(a.z), __int2half_rn(a.w));
    h[2] = __halves2half2(__int2half_rn(b.x), __int2half_rn(b.y));
    h[3] = __halves2half2(__int2half_rn(b.z), __int2half_rn(b.w));
    *reinterpret_cast<uint4*>(g_Ah + idx) = *reinterpret_cast<uint4*>(h);
}

// ---------------------------------------------------------------------------
// Kernel 1: ht = leakyrelu(h @ W)
// ---------------------------------------------------------------------------
__global__ __launch_bounds__(256) void k_proj(const float* __restrict__ h,
                                              const float* __restrict__ W) {
    __shared__ float As[32][64];
    __shared__ float Bs[32][128];
    const int tid = threadIdx.x;
    const int m0 = blockIdx.x * 64;
    const int n0 = blockIdx.y * 128;
    const int trow = tid >> 5;
    const int tcol = tid & 31;

    float acc[8][4];
#pragma unroll
    for (int r = 0; r < 8; r++)
#pragma unroll
        for (int n = 0; n < 4; n++) acc[r][n] = 0.f;

    for (int k0 = 0; k0 < FF; k0 += 32) {
        {
            const int r = tid >> 2;
            const int kc = (tid & 3) * 8;
            const float4* src = reinterpret_cast<const float4*>(
                h + (size_t)(m0 + r) * FF + k0 + kc);
            float4 v0 = src[0], v1 = src[1];
            As[kc + 0][r] = v0.x; As[kc + 1][r] = v0.y;
            As[kc + 2][r] = v0.z; As[kc + 3][r] = v0.w;
            As[kc + 4][r] = v1.x; As[kc + 5][r] = v1.y;
            As[kc + 6][r] = v1.z; As[kc + 7][r] = v1.w;
        }
#pragma unroll
        for (int idx = tid * 4; idx < 32 * 128; idx += 1024) {
            const int kk = idx >> 7;
            const int n = idx & 127;
            *reinterpret_cast<float4*>(&Bs[kk][n]) =
                *reinterpret_cast<const float4*>(W + (size_t)(k0 + kk) * CC + n0 + n);
        }
        __syncthreads();
#pragma unroll
        for (int kk = 0; kk < 32; kk++) {
            float4 a0 = *reinterpret_cast<float4*>(&As[kk][trow * 8]);
            float4 a1 = *reinterpret_cast<float4*>(&As[kk][trow * 8 + 4]);
            float4 bb = *reinterpret_cast<float4*>(&Bs[kk][tcol * 4]);
            float am[8] = {a0.x, a0.y, a0.z, a0.w, a1.x, a1.y, a1.z, a1.w};
            float bn[4] = {bb.x, bb.y, bb.z, bb.w};
#pragma unroll
            for (int r = 0; r < 8; r++)
#pragma unroll
                for (int n = 0; n < 4; n++) acc[r][n] += am[r] * bn[n];
        }
        __syncthreads();
    }
#pragma unroll
    for (int r = 0; r < 8; r++) {
        const size_t off = (size_t)(m0 + trow * 8 + r) * CC + n0 + tcol * 4;
        float4 o; float x;
        x = acc[r][0]; o.x = (x >= 0.f) ? x : 0.1f * x;
        x = acc[r][1]; o.y = (x >= 0.f) ? x : 0.1f * x;
        x = acc[r][2]; o.z = (x >= 0.f) ? x : 0.1f * x;
        x = acc[r][3]; o.w = (x >= 0.f) ? x : 0.1f * x;
        *reinterpret_cast<float4*>(&g_ht[off]) = o;
    }
}

// ---------------------------------------------------------------------------
// Kernel 2: tgt[h][j]
// ---------------------------------------------------------------------------
__global__ __launch_bounds__(256) void k_tgt(const float* __restrict__ a) {
    const int gw = blockIdx.x * 8 + (threadIdx.x >> 5);
    const int lane = threadIdx.x & 31;
    const int h = gw & 3;
    const int j = gw >> 2;
    float4 x = *reinterpret_cast<const float4*>(g_ht + (size_t)j * CC + h * DD + lane * 4);
    float4 av = *reinterpret_cast<const float4*>(a + h * 256 + 128 + lane * 4);
    float s = x.x * av.x + x.y * av.y + x.z * av.z + x.w * av.w;
#pragma unroll
    for (int o = 16; o; o >>= 1) s += __shfl_xor_sync(0xFFFFFFFFu, s, o);
    if (lane == 0) g_tgt[h * NN + j] = s;
}

// ---------------------------------------------------------------------------
// Kernel 3: per-head max
// ---------------------------------------------------------------------------
__global__ __launch_bounds__(256) void k_max() {
    __shared__ float red[256];
    const int h = blockIdx.x;
    const int tid = threadIdx.x;
    float m = -1e30f;
    for (int j = tid; j < NN; j += 256) m = fmaxf(m, g_tgt[h * NN + j]);
    red[tid] = m;
    __syncthreads();
#pragma unroll
    for (int s = 128; s; s >>= 1) {
        if (tid < s) red[tid] = fmaxf(red[tid], red[tid + s]);
        __syncthreads();
    }
    if (tid == 0) g_mh[h] = red[0];
}

// ---------------------------------------------------------------------------
// Kernel 4: w = exp(tgt-mh); also fp16 wT (rows 4..15 zero)
// ---------------------------------------------------------------------------
__global__ __launch_bounds__(256) void k_expw() {
    int idx = blockIdx.x * 256 + threadIdx.x;   // 0 .. 16*NN-1
    int h = idx >> 13;
    if (h < 4) {
        float w = expf(g_tgt[idx] - g_mh[h]);
        g_w[idx] = w;
        g_wT[idx] = __float2half(w);
    } else {
        g_wT[idx] = __float2half(0.f);
    }
}

// ---------------------------------------------------------------------------
// Kernel 5: build transposed fp16 V: g_VT[n][j] = w[n>>7][j] * ht[j][n]
// ---------------------------------------------------------------------------
__global__ __launch_bounds__(256) void k_buildVT() {
    __shared__ float ts[32][129];
    const int tid = threadIdx.x;
    const int j0 = blockIdx.x * 128;
    const int n0 = blockIdx.y * 32;
#pragma unroll
    for (int r = 0; r < 16; r++) {
        int idx = r * 256 + tid;
        int jl = idx >> 5;
        int nl = idx & 31;
        ts[nl][jl] = g_ht[(size_t)(j0 + jl) * CC + n0 + nl];
    }
    __syncthreads();
    const int h = n0 >> 7;
#pragma unroll
    for (int r = 0; r < 2; r++) {
        int v = r * 256 + tid;
        int nl = v >> 4;
        int j8 = (v & 15) * 8;
        __half out[8];
#pragma unroll
        for (int e = 0; e < 8; e++)
            out[e] = __float2half(ts[nl][j8 + e] * g_w[(size_t)h * NN + j0 + j8 + e]);
        *reinterpret_cast<uint4*>(g_VT + (size_t)(n0 + nl) * NN + j0 + j8) =
            *reinterpret_cast<uint4*>(out);
    }
}

// ---------------------------------------------------------------------------
// Kernel 6: O = A @ V via mma.sync. CTA 256x128, 8 warps, warp 64x64.
// grid (4 n fast, 32 m) = 128 CTAs (one/SM). n-tile 0 also computes den.
// ---------------------------------------------------------------------------
__device__ __forceinline__ void load_stage(int t, uint32_t sb, int m0, int n0, int tid) {
    const int k0 = t * KST;
    const uint32_t base = sb + (t % NST) * STAGE;
#pragma unroll
    for (int i = 0; i < 12; i++) {
        int idx = i * 256 + tid;       // 0..3071
        if (idx < 2048) {              // A: 256 rows x 8 chunks
            int r = idx >> 3, c = idx & 7;
            cp16(base + r * ROWB + c * 16,
                 g_Ah + (size_t)(m0 + r) * NN + k0 + c * 8);
        } else {                       // B: 128 rows x 8 chunks
            int j = idx - 2048;
            int r = j >> 3, c = j & 7;
            cp16(base + A_BYTES + r * ROWB + c * 16,
                 g_VT + (size_t)(n0 + r) * NN + k0 + c * 8);
        }
    }
    if (tid < 128) {                   // B2 (wT): 16 rows x 8 chunks
        int r = tid >> 3, c = tid & 7;
        cp16(base + A_BYTES + B_BYTES + r * ROWB + c * 16,
             g_wT + (size_t)r * NN + k0 + c * 8);
    }
}

__global__ __launch_bounds__(256, 1) void k_aggr_mma() {
    extern __shared__ __align__(128) char smem[];
    const uint32_t sb = smem_u32(smem);
    const int tid = threadIdx.x;
    const int lane = tid & 31;
    const int wid = tid >> 5;
    const int wm = wid & 3;        // 4 m positions x 64 rows
    const int wn = wid >> 2;       // 2 n positions x 64 cols
    const int n0 = blockIdx.x * 128;
    const int m0 = blockIdx.y * 256;
    const bool do_den = (blockIdx.x == 0) && (wn == 0);

    float acc[4][8][4];
#pragma unroll
    for (int f = 0; f < 4; f++)
#pragma unroll
        for (int g = 0; g < 8; g++)
#pragma unroll
            for (int e = 0; e < 4; e++) acc[f][g][e] = 0.f;
    float dacc[4][4];
#pragma unroll
    for (int f = 0; f < 4; f++)
#pragma unroll
        for (int e = 0; e < 4; e++) dacc[f][e] = 0.f;

#pragma unroll
    for (int s = 0; s < NST; s++) {
        load_stage(s, sb, m0, n0, tid);
        cp_commit();
    }

    const int lr = lane & 15;
    const int lk = (lane >> 4) * 8;

    const int S = NN / KST;  // 128
    for (int s = 0; s < S; s++) {
        asm volatile("cp.async.wait_group %0;" :: "n"(NST - 1) : "memory");
        __syncthreads();
        const uint32_t st = sb + (s % NST) * STAGE;
#pragma unroll
        for (int kk = 0; kk < KST / 16; kk++) {
            uint32_t af[4][4], bf[4][4];
#pragma unroll
            for (int f = 0; f < 4; f++) {
                int r = wm * 64 + f * 16 + lr;
                ldsm4(af[f][0], af[f][1], af[f][2], af[f][3],
                      st + r * ROWB + (kk * 16 + lk) * 2);
            }
#pragma unroll
            for (int g = 0; g < 4; g++) {
                int n = wn * 64 + g * 16 + lr;
                ldsm4(bf[g][0], bf[g][1], bf[g][2], bf[g][3],
                      st + A_BYTES + n * ROWB + (kk * 16 + lk) * 2);
            }
#pragma unroll
            for (int f = 0; f < 4; f++)
#pragma unroll
                for (int g = 0; g < 4; g++) {
                    mma16816(acc[f][g * 2 + 0], af[f], bf[g][0], bf[g][2]);
                    mma16816(acc[f][g * 2 + 1], af[f], bf[g][1], bf[g][3]);
                }
            if (do_den) {
                uint32_t bw[4];
                ldsm4(bw[0], bw[1], bw[2], bw[3],
                      st + A_BYTES + B_BYTES + lr * ROWB + (kk * 16 + lk) * 2);
#pragma unroll
                for (int f = 0; f < 4; f++)
                    mma16816(dacc[f], af[f], bw[0], bw[2]);
            }
        }
        __syncthreads();
        if (s + NST < S) {
            load_stage(s + NST, sb, m0, n0, tid);
            cp_commit();
        }
    }

    // epilogue: numerators
#pragma unroll
    for (int f = 0; f < 4; f++) {
        const int row = m0 + wm * 64 + f * 16 + (lane >> 2);
#pragma unroll
        for (int g = 0; g < 8; g++) {
            const int col = n0 + wn * 64 + g * 8 + (lane & 3) * 2;
            float2 v0 = {acc[f][g][0], acc[f][g][1]};
            float2 v1 = {acc[f][g][2], acc[f][g][3]};
            *reinterpret_cast<float2*>(g_O + (size_t)row * CC + col) = v0;
            *reinterpret_cast<float2*>(g_O + (size_t)(row + 8) * CC + col) = v1;
        }
    }
    // denominators (cols 0..3 of the n8 fragment = heads)
    if (do_den) {
        const int c2 = (lane & 3) * 2;
        if (c2 < 4) {
#pragma unroll
            for (int f = 0; f < 4; f++) {
                const int row = m0 + wm * 64 + f * 16 + (lane >> 2);
                g_den[row * 4 + c2 + 0] = dacc[f][0];
                g_den[row * 4 + c2 + 1] = dacc[f][1];
                g_den[(row + 8) * 4 + c2 + 0] = dacc[f][2];
                g_den[(row + 8) * 4 + c2 + 1] = dacc[f][3];
            }
        }
    }
}

// ---------------------------------------------------------------------------
// Kernel 7: out[i][d] = 0.25 * sum_h num[h]/den[h]
// ---------------------------------------------------------------------------
__global__ __launch_bounds__(128) void k_out(float* __restrict__ out) {
    const int i = blockIdx.x;
    const int d = threadIdx.x;
    __shared__ float inv[4];
    if (d < 4) inv[d] = 1.0f / g_den[i * 4 + d];
    __syncthreads();
    float s = 0.f;
#pragma unroll
    for (int h = 0; h < 4; h++) s += g_O[(size_t)i * CC + h * DD + d] * inv[h];
    out[(size_t)i * DD + d] = 0.25f * s;
}

// ---------------------------------------------------------------------------
extern "C" void kernel_launch(void* const* d_in, const int* in_sizes, int n_in,
                              void* d_out, int out_size) {
    const float* h   = (const float*)d_in[0];
    const int*   adj = (const int*)d_in[1];
    const float* W   = (const float*)d_in[2];
    const float* a   = (const float*)d_in[3];
    float* out = (float*)d_out;

    static cudaStream_t s1;
    static cudaEvent_t e0, e1;
    static int init_done = 0;
    if (!init_done) {
        cudaFuncSetAttribute(k_aggr_mma, cudaFuncAttributeMaxDynamicSharedMemorySize, SMEMB);
        cudaStreamCreateWithFlags(&s1, cudaStreamNonBlocking);
        cudaEventCreateWithFlags(&e0, cudaEventDisableTiming);
        cudaEventCreateWithFlags(&e1, cudaEventDisableTiming);
        init_done = 1;
    }

    // fork: conv on side stream, prep chain on main
    cudaEventRecord(e0, 0);
    cudaStreamWaitEvent(s1, e0, 0);
    k_conv<<<32768, 256, 0, s1>>>(adj);
    cudaEventRecord(e1, s1);

    k_proj<<<dim3(128, 4), 256>>>(h, W);
    k_tgt<<<4096, 256>>>(a);
    k_max<<<4, 256>>>();
    k_expw<<<512, 256>>>();
    k_buildVT<<<dim3(64, 16), 256>>>();

    // join before aggregation (needs g_Ah)
    cudaStreamWaitEvent(0, e1, 0);
    k_aggr_mma<<<dim3(4, 32), 256, SMEMB>>>();
    k_out<<<8192, 128>>>(out);
}